// round 5
// baseline (speedup 1.0000x reference)
#include <cuda_runtime.h>
#include <cuda_bf16.h>
#include <math.h>

// Problem constants (shapes fixed by the reference)
#define MAX_N 50000
#define MAX_E 800000
#define MAX_G 16
#define NODE_DIM 128
#define HID 64
#define HEADS 3
#define FDIM 192            // HEADS*HID
#define NEG_SLOPE 0.2f

// ---------------- device scratch (static, no runtime alloc) ----------------
__device__ __nv_bfloat162 g_featb[(size_t)MAX_N * 96];  // 19.2 MB (bf16 feat)
__device__ float4 g_el4[MAX_N];                          // padded el (x,y,z used)
__device__ float4 g_er4[MAX_N];
__device__ int    g_deg[MAX_N];
__device__ int    g_rowoff[MAX_N + 1];
__device__ int    g_cursor[MAX_N];
__device__ int    g_csrsrc[MAX_E];
__device__ float  g_pool[MAX_G * HID];
__device__ float  g_gcount[MAX_G];

// ---------------- helpers ----------------
__device__ __forceinline__ void fma2(unsigned long long& d,
                                     unsigned long long a,
                                     unsigned long long b) {
    // packed 2x fp32 fma (FFMA2) — only reachable via PTX fma.rn.f32x2
    asm("fma.rn.f32x2 %0, %1, %2, %0;" : "+l"(d) : "l"(a), "l"(b));
}

__device__ __forceinline__ float leaky(float x) {
    return x > 0.f ? x : NEG_SLOPE * x;
}

// ---------------- init ----------------
__global__ void k_init(int N, int G) {
    int i = blockIdx.x * blockDim.x + threadIdx.x;
    int stride = gridDim.x * blockDim.x;
    for (int j = i; j < N; j += stride) g_deg[j] = 0;
    if (i < G * HID) g_pool[i] = 0.f;
    if (i < G) g_gcount[i] = 0.f;
}

// ---------------- K1: feat = h @ fc_w^T (FFMA2), fused el/er, bf16 out ----
// block: 128 threads, 128 nodes (1 node/thread).
// smem: h tile node-major [128][132] (pad keeps LDS.128 conflict-free &
//       16B-aligned: 132*4=528 = 33*16), weight quarter [48 cols][128 k],
//       attn_l/attn_r flat [192] each.
#define K1_HS_FLOATS (128 * 132)
#define K1_WS_FLOATS (48 * 128)
#define K1_SMEM_BYTES ((K1_HS_FLOATS + K1_WS_FLOATS + 2 * FDIM) * 4)

__global__ void __launch_bounds__(128) k_gemm(
    const float* __restrict__ h, const float* __restrict__ fc_w,
    const float* __restrict__ attn_l, const float* __restrict__ attn_r, int N)
{
    extern __shared__ float sm[];
    float*  h_s = sm;                               // [128][132]
    float*  w_s = sm + K1_HS_FLOATS;                // [48][128] k-contiguous
    float*  al  = sm + K1_HS_FLOATS + K1_WS_FLOATS; // [192]
    float*  ar  = al + FDIM;                        // [192]

    const int t = threadIdx.x;
    const int node = blockIdx.x * 128 + t;
    const bool valid = node < N;

    // cooperative h-tile load: row-by-row, coalesced, stored node-major
    const int base = blockIdx.x * 128;
    #pragma unroll 4
    for (int r = 0; r < 128; r++) {
        int n0 = base + r;
        float v = (n0 < N) ? h[(size_t)n0 * NODE_DIM + t] : 0.f;
        h_s[r * 132 + t] = v;
    }
    for (int i = t; i < FDIM; i += 128) { al[i] = attn_l[i]; ar[i] = attn_r[i]; }

    float el_acc[HEADS] = {0.f, 0.f, 0.f};
    float er_acc[HEADS] = {0.f, 0.f, 0.f};

    const float4* fw4 = (const float4*)fc_w;
    float4* w_s4 = (float4*)w_s;

    #pragma unroll
    for (int q = 0; q < 4; q++) {
        __syncthreads();   // h_s ready (q=0) / previous quarter done (q>0)
        // load weight quarter: rows q*48 .. q*48+47, k-contiguous
        for (int i = t; i < 48 * 32; i += 128)
            w_s4[i] = fw4[q * 48 * 32 + i];
        __syncthreads();

        unsigned long long acc2[48];
        #pragma unroll
        for (int i = 0; i < 48; i++) acc2[i] = 0ull;  // two packed +0.0f

        const ulonglong2* w8 = (const ulonglong2*)w_s;
        #pragma unroll 2
        for (int k4 = 0; k4 < 32; k4++) {
            ulonglong2 hv = *(const ulonglong2*)&h_s[t * 132 + k4 * 4];
            #pragma unroll
            for (int c = 0; c < 48; c++) {
                ulonglong2 w = w8[c * 32 + k4];
                fma2(acc2[c], hv.x, w.x);
                fma2(acc2[c], hv.y, w.y);
            }
        }

        const int c0 = q * 48;
        float v[48];
        #pragma unroll
        for (int i = 0; i < 48; i++) {
            float2 f = *(float2*)&acc2[i];
            v[i] = f.x + f.y;                 // fold even/odd-k partials
        }
        #pragma unroll
        for (int i = 0; i < 48; i++) {
            const int c = c0 + i;
            const int hd = c >> 6;            // compile-time (q, i unrolled)
            el_acc[hd] += v[i] * al[c];
            er_acc[hd] += v[i] * ar[c];
        }
        if (valid) {
            __nv_bfloat162* fout = &g_featb[(size_t)node * 96 + (c0 >> 1)];
            #pragma unroll
            for (int i = 0; i < 48; i += 2)
                fout[i >> 1] = __floats2bfloat162_rn(v[i], v[i + 1]);
        }
    }

    if (valid) {
        g_el4[node] = make_float4(el_acc[0], el_acc[1], el_acc[2], 0.f);
        g_er4[node] = make_float4(er_acc[0], er_acc[1], er_acc[2], 0.f);
    }
}

// ---------------- K2: CSR build ----------------
__global__ void k_degree(const int* __restrict__ dst, int E) {
    int i = blockIdx.x * blockDim.x + threadIdx.x;
    if (i < E) atomicAdd(&g_deg[dst[i]], 1);
}

// single-block chunked exclusive scan: 49 contiguous elems/thread,
// one shuffle-based block scan of per-thread sums, sequential write-back.
__global__ void __launch_bounds__(1024) k_scan(int N) {
    __shared__ int wsum[32];
    const int t = threadIdx.x, lane = t & 31, w = t >> 5;
    const int CH = (N + 1023) >> 10;
    const int start = t * CH;

    int sum = 0;
    for (int j = 0; j < CH; j++) {
        int idx = start + j;
        if (idx < N) sum += g_deg[idx];
    }
    int x = sum;
    #pragma unroll
    for (int o = 1; o < 32; o <<= 1) {
        int y = __shfl_up_sync(0xffffffffu, x, o);
        if (lane >= o) x += y;
    }
    if (lane == 31) wsum[w] = x;
    __syncthreads();
    if (w == 0) {
        int s = wsum[lane], sc = s;
        #pragma unroll
        for (int o = 1; o < 32; o <<= 1) {
            int y = __shfl_up_sync(0xffffffffu, sc, o);
            if (lane >= o) sc += y;
        }
        wsum[lane] = sc - s;     // exclusive warp offsets
    }
    __syncthreads();

    int run = (x - sum) + wsum[w];   // block-exclusive prefix for this thread
    for (int j = 0; j < CH; j++) {
        int idx = start + j;
        if (idx < N) {
            int d = g_deg[idx];
            g_rowoff[idx] = run;
            g_cursor[idx] = run;
            run += d;
        }
    }
    if (t == 1023) g_rowoff[N] = run;   // thread 1023's chunk is past N
}

__global__ void k_scatter(const int* __restrict__ src, const int* __restrict__ dst, int E) {
    int i = blockIdx.x * blockDim.x + threadIdx.x;
    if (i < E) {
        int d = dst[i];
        int pos = atomicAdd(&g_cursor[d], 1);
        g_csrsrc[pos] = src[i];
    }
}

// ---------------- K3: fused GAT softmax + aggregation + pool (1 pass) ------
// warp per destination node; lane l owns head-dims (2l, 2l+1) of each head.
// softmax computed WITHOUT max-shift (|el+er| ~ 7 max; ratios invariant).
__global__ void __launch_bounds__(256) k_gat(
    const int* __restrict__ graph_id, const float* __restrict__ bias, int N)
{
    const int node = (blockIdx.x * blockDim.x + threadIdx.x) >> 5;
    const int lane = threadIdx.x & 31;
    if (node >= N) return;
    const int begin = g_rowoff[node];
    const int end   = g_rowoff[node + 1];

    const float4 er = g_er4[node];

    float s0 = 0.f, s1 = 0.f, s2 = 0.f;
    float a0 = 0.f, a1 = 0.f, a2 = 0.f, a3 = 0.f, a4 = 0.f, a5 = 0.f;
    #pragma unroll 4
    for (int i = begin; i < end; i++) {
        int s = g_csrsrc[i];
        float4 el = g_el4[s];                       // one LDG.128 broadcast
        float e0 = __expf(leaky(el.x + er.x));
        float e1 = __expf(leaky(el.y + er.y));
        float e2 = __expf(leaky(el.z + er.z));
        s0 += e0; s1 += e1; s2 += e2;
        const __nv_bfloat162* fr = &g_featb[(size_t)s * 96];
        float2 f0 = __bfloat1622float2(fr[lane]);        // head0 dims 2l,2l+1
        float2 f1 = __bfloat1622float2(fr[32 + lane]);   // head1
        float2 f2 = __bfloat1622float2(fr[64 + lane]);   // head2
        a0 += e0 * f0.x;  a1 += e0 * f0.y;
        a2 += e1 * f1.x;  a3 += e1 * f1.y;
        a4 += e2 * f2.x;  a5 += e2 * f2.y;
    }

    const bool has = end > begin;
    const float i0 = has ? 1.f / s0 : 0.f;
    const float i1 = has ? 1.f / s1 : 0.f;
    const float i2 = has ? 1.f / s2 : 0.f;

    const int d0 = 2 * lane, d1 = 2 * lane + 1;
    const float third = 1.f / 3.f;
    float hd0 = (a0 * i0 + a2 * i1 + a4 * i2
                 + bias[d0] + bias[64 + d0] + bias[128 + d0]) * third;
    float hd1 = (a1 * i0 + a3 * i1 + a5 * i2
                 + bias[d1] + bias[64 + d1] + bias[128 + d1]) * third;

    const int g = graph_id[node];
    atomicAdd(&g_pool[g * HID + d0], hd0);
    atomicAdd(&g_pool[g * HID + d1], hd1);
    if (lane == 0) atomicAdd(&g_gcount[g], 1.f);
}

// ---------------- K4: final MLP + sigmoid ----------------
__global__ void k_final(
    const float* __restrict__ z, const float* __restrict__ lin1_w,
    const float* __restrict__ lin1_b, const float* __restrict__ lin2_w,
    const float* __restrict__ lin2_b, float* __restrict__ out, int G)
{
    const int w = threadIdx.x >> 5;
    const int lane = threadIdx.x & 31;
    if (w >= G) return;

    float z1a = lin1_b[lane], z1b = lin1_b[lane + 32];
    const float* zr = &z[w * 128];
    const float* w1a = &lin1_w[lane * 128];
    const float* w1b = &lin1_w[(lane + 32) * 128];
    #pragma unroll 4
    for (int k = 0; k < 128; k++) {
        float zv = zr[k];
        z1a += zv * w1a[k];
        z1b += zv * w1b[k];
    }

    float cnt = g_gcount[w];
    float invc = 1.f / fmaxf(cnt, 1.f);
    float pa = g_pool[w * HID + lane] * invc;
    float pb = g_pool[w * HID + 32 + lane] * invc;

    float part = lin2_w[lane] * pa + lin2_w[32 + lane] * pb
               + lin2_w[64 + lane] * z1a + lin2_w[96 + lane] * z1b;
    #pragma unroll
    for (int o = 16; o > 0; o >>= 1)
        part += __shfl_down_sync(0xffffffffu, part, o);

    if (lane == 0) {
        float v = part + lin2_b[0];
        out[w] = 1.f / (1.f + expf(-v));
    }
}

// ---------------- launch ----------------
extern "C" void kernel_launch(void* const* d_in, const int* in_sizes, int n_in,
                              void* d_out, int out_size)
{
    const float* h        = (const float*)d_in[0];
    const float* z        = (const float*)d_in[1];
    const int*   src      = (const int*)  d_in[2];
    const int*   dst      = (const int*)  d_in[3];
    const int*   graph_id = (const int*)  d_in[4];
    const float* fc_w     = (const float*)d_in[5];
    const float* attn_l   = (const float*)d_in[6];
    const float* attn_r   = (const float*)d_in[7];
    const float* bias     = (const float*)d_in[8];
    const float* lin1_w   = (const float*)d_in[9];
    const float* lin1_b   = (const float*)d_in[10];
    const float* lin2_w   = (const float*)d_in[11];
    const float* lin2_b   = (const float*)d_in[12];

    const int N = in_sizes[0] / NODE_DIM;   // 50000
    const int E = in_sizes[2];              // 800000
    const int G = in_sizes[1] / 128;        // 16

    cudaFuncSetAttribute(k_gemm, cudaFuncAttributeMaxDynamicSharedMemorySize,
                         K1_SMEM_BYTES);

    k_init<<<64, 256>>>(N, G);
    k_gemm<<<(N + 127) / 128, 128, K1_SMEM_BYTES>>>(h, fc_w, attn_l, attn_r, N);
    k_degree<<<(E + 255) / 256, 256>>>(dst, E);
    k_scan<<<1, 1024>>>(N);
    k_scatter<<<(E + 255) / 256, 256>>>(src, dst, E);
    {
        int blocks = (N * 32 + 255) / 256;
        k_gat<<<blocks, 256>>>(graph_id, bias, N);
    }
    k_final<<<1, 32 * G>>>(z, lin1_w, lin1_b, lin2_w, lin2_b, (float*)d_out, G);
}

// round 6
// speedup vs baseline: 1.1503x; 1.1503x over previous
#include <cuda_runtime.h>
#include <cuda_bf16.h>
#include <math.h>

// Problem constants (shapes fixed by the reference)
#define MAX_N 50000
#define MAX_E 800000
#define MAX_G 16
#define NODE_DIM 128
#define HID 64
#define HEADS 3
#define FDIM 192            // HEADS*HID
#define NEG_SLOPE 0.2f
#define SCAN_B 1024
#define MAX_BLKS 64         // ceil(50000/1024)=49

// ---------------- device scratch (static, no runtime alloc) ----------------
__device__ __nv_bfloat162 g_featb[(size_t)MAX_N * 96];  // 19.2 MB (bf16 feat)
__device__ float4 g_el4[MAX_N];                          // padded el (x,y,z used)
__device__ float4 g_er4[MAX_N];
__device__ int    g_deg[MAX_N];
__device__ int    g_bsum[MAX_BLKS];
__device__ int    g_rowoff[MAX_N + 1];
__device__ int    g_cursor[MAX_N];
__device__ int    g_csrsrc[MAX_E];
__device__ float  g_pool[MAX_G * HID];
__device__ float  g_gcount[MAX_G];

// ---------------- helpers ----------------
__device__ __forceinline__ void fma2(unsigned long long& d,
                                     unsigned long long a,
                                     unsigned long long b) {
    // packed 2x fp32 fma (FFMA2) — only reachable via PTX fma.rn.f32x2
    asm("fma.rn.f32x2 %0, %1, %2, %0;" : "+l"(d) : "l"(a), "l"(b));
}

__device__ __forceinline__ float leaky(float x) {
    return x > 0.f ? x : NEG_SLOPE * x;
}

// ---------------- init ----------------
__global__ void k_init(int N, int G) {
    int i = blockIdx.x * blockDim.x + threadIdx.x;
    int stride = gridDim.x * blockDim.x;
    for (int j = i; j < N; j += stride) g_deg[j] = 0;
    if (i < G * HID) g_pool[i] = 0.f;
    if (i < G) g_gcount[i] = 0.f;
}

// ---------------- CSR phase 1: degree histogram ----------------
__global__ void k_degree(const int* __restrict__ dst, int E) {
    int i = blockIdx.x * blockDim.x + threadIdx.x;
    if (i < E) atomicAdd(&g_deg[dst[i]], 1);
}

// ---------------- CSR phase 2a: per-block (1024-tile) sums, coalesced ------
__global__ void __launch_bounds__(SCAN_B) k_scan_partial(int N) {
    __shared__ int ws[32];
    const int t = threadIdx.x, lane = t & 31, w = t >> 5;
    int idx = blockIdx.x * SCAN_B + t;
    int v = (idx < N) ? g_deg[idx] : 0;
    #pragma unroll
    for (int o = 16; o > 0; o >>= 1) v += __shfl_down_sync(0xffffffffu, v, o);
    if (lane == 0) ws[w] = v;
    __syncthreads();
    if (w == 0) {
        int s = ws[lane];
        #pragma unroll
        for (int o = 16; o > 0; o >>= 1) s += __shfl_down_sync(0xffffffffu, s, o);
        if (lane == 0) g_bsum[blockIdx.x] = s;
    }
}

// ---------------- CSR phase 2b: block-local scan + top-scan + write --------
__global__ void __launch_bounds__(SCAN_B) k_scan_final(int N) {
    __shared__ int soff[MAX_BLKS];
    __shared__ int wsum[32];
    const int t = threadIdx.x, lane = t & 31, w = t >> 5;
    const int nb = gridDim.x;

    // warp 0: exclusive scan of up to 64 block sums (redundant per block)
    if (w == 0) {
        int v0 = (lane < nb) ? g_bsum[lane] : 0;
        int v1 = (lane + 32 < nb) ? g_bsum[lane + 32] : 0;
        int s0 = v0, s1 = v1;
        #pragma unroll
        for (int o = 1; o < 32; o <<= 1) {
            int y = __shfl_up_sync(0xffffffffu, s0, o);
            if (lane >= o) s0 += y;
            int y1 = __shfl_up_sync(0xffffffffu, s1, o);
            if (lane >= o) s1 += y1;
        }
        int tot0 = __shfl_sync(0xffffffffu, s0, 31);
        s1 += tot0;
        soff[lane] = s0 - v0;
        soff[lane + 32] = s1 - v1;
    }
    __syncthreads();
    const int off = soff[blockIdx.x];

    // block-local exclusive scan of this 1024-tile (coalesced reload of deg)
    int idx = blockIdx.x * SCAN_B + t;
    int v = (idx < N) ? g_deg[idx] : 0;
    int x = v;
    #pragma unroll
    for (int o = 1; o < 32; o <<= 1) {
        int y = __shfl_up_sync(0xffffffffu, x, o);
        if (lane >= o) x += y;
    }
    if (lane == 31) wsum[w] = x;
    __syncthreads();
    if (w == 0) {
        int s = wsum[lane], sc = s;
        #pragma unroll
        for (int o = 1; o < 32; o <<= 1) {
            int y = __shfl_up_sync(0xffffffffu, sc, o);
            if (lane >= o) sc += y;
        }
        wsum[lane] = sc - s;
    }
    __syncthreads();

    int excl = (x - v) + wsum[w] + off;
    if (idx < N) {
        g_rowoff[idx] = excl;
        g_cursor[idx] = excl;
        if (idx == N - 1) g_rowoff[N] = excl + v;
    }
}

// ---------------- CSR phase 3: scatter ----------------
__global__ void k_scatter(const int* __restrict__ src, const int* __restrict__ dst, int E) {
    int i = blockIdx.x * blockDim.x + threadIdx.x;
    if (i < E) {
        int d = dst[i];
        int pos = atomicAdd(&g_cursor[d], 1);
        g_csrsrc[pos] = src[i];
    }
}

// ---------------- K1: feat = h @ fc_w^T (FFMA2), fused el/er, bf16 out ----
// block: 128 threads, 128 nodes (1 node/thread).
// smem: h tile node-major [128][132] (pad keeps LDS.128 conflict-free &
//       16B-aligned), weight quarter [48 cols][128 k], attn vecs.
#define K1_HS_FLOATS (128 * 132)
#define K1_WS_FLOATS (48 * 128)
#define K1_SMEM_BYTES ((K1_HS_FLOATS + K1_WS_FLOATS + 2 * FDIM) * 4)

__global__ void __launch_bounds__(128) k_gemm(
    const float* __restrict__ h, const float* __restrict__ fc_w,
    const float* __restrict__ attn_l, const float* __restrict__ attn_r, int N)
{
    extern __shared__ float sm[];
    float*  h_s = sm;                               // [128][132]
    float*  w_s = sm + K1_HS_FLOATS;                // [48][128] k-contiguous
    float*  al  = sm + K1_HS_FLOATS + K1_WS_FLOATS; // [192]
    float*  ar  = al + FDIM;                        // [192]

    const int t = threadIdx.x;
    const int node = blockIdx.x * 128 + t;
    const bool valid = node < N;

    const int base = blockIdx.x * 128;
    #pragma unroll 4
    for (int r = 0; r < 128; r++) {
        int n0 = base + r;
        float v = (n0 < N) ? h[(size_t)n0 * NODE_DIM + t] : 0.f;
        h_s[r * 132 + t] = v;
    }
    for (int i = t; i < FDIM; i += 128) { al[i] = attn_l[i]; ar[i] = attn_r[i]; }

    float el_acc[HEADS] = {0.f, 0.f, 0.f};
    float er_acc[HEADS] = {0.f, 0.f, 0.f};

    const float4* fw4 = (const float4*)fc_w;
    float4* w_s4 = (float4*)w_s;
    uint4* frow = (uint4*)&g_featb[(size_t)(valid ? node : 0) * 96];

    #pragma unroll
    for (int q = 0; q < 4; q++) {
        __syncthreads();
        for (int i = t; i < 48 * 32; i += 128)
            w_s4[i] = fw4[q * 48 * 32 + i];
        __syncthreads();

        unsigned long long acc2[48];
        #pragma unroll
        for (int i = 0; i < 48; i++) acc2[i] = 0ull;

        const ulonglong2* w8 = (const ulonglong2*)w_s;
        #pragma unroll 2
        for (int k4 = 0; k4 < 32; k4++) {
            ulonglong2 hv = *(const ulonglong2*)&h_s[t * 132 + k4 * 4];
            #pragma unroll
            for (int c = 0; c < 48; c++) {
                ulonglong2 w = w8[c * 32 + k4];
                fma2(acc2[c], hv.x, w.x);
                fma2(acc2[c], hv.y, w.y);
            }
        }

        const int c0 = q * 48;
        #pragma unroll
        for (int i = 0; i < 48; i += 8) {
            float v[8];
            #pragma unroll
            for (int j = 0; j < 8; j++) {
                float2 f = *(float2*)&acc2[i + j];
                v[j] = f.x + f.y;             // fold even/odd-k partials
            }
            const int c = c0 + i;
            const int hd = c >> 6;            // 8-col groups never straddle heads
            #pragma unroll
            for (int j = 0; j < 8; j++) {
                el_acc[hd] += v[j] * al[c + j];
                er_acc[hd] += v[j] * ar[c + j];
            }
            if (valid) {
                __nv_bfloat162 b0 = __floats2bfloat162_rn(v[0], v[1]);
                __nv_bfloat162 b1 = __floats2bfloat162_rn(v[2], v[3]);
                __nv_bfloat162 b2 = __floats2bfloat162_rn(v[4], v[5]);
                __nv_bfloat162 b3 = __floats2bfloat162_rn(v[6], v[7]);
                uint4 u;
                u.x = *(unsigned int*)&b0; u.y = *(unsigned int*)&b1;
                u.z = *(unsigned int*)&b2; u.w = *(unsigned int*)&b3;
                frow[c >> 3] = u;
            }
        }
    }

    if (valid) {
        g_el4[node] = make_float4(el_acc[0], el_acc[1], el_acc[2], 0.f);
        g_er4[node] = make_float4(er_acc[0], er_acc[1], er_acc[2], 0.f);
    }
}

// ---------------- K3: fused GAT softmax + aggregation + pool (1 pass) ------
// warp per destination node; lane l owns head-dims (2l, 2l+1) of each head.
// softmax computed WITHOUT max-shift (|el+er| small; ratios invariant).
// csrsrc read coalesced (LDG.128 per 32 edges) and broadcast via shfl.
__global__ void __launch_bounds__(256) k_gat(
    const int* __restrict__ graph_id, const float* __restrict__ bias, int N)
{
    const int node = (blockIdx.x * blockDim.x + threadIdx.x) >> 5;
    const int lane = threadIdx.x & 31;
    if (node >= N) return;
    const int begin = g_rowoff[node];
    const int end   = g_rowoff[node + 1];

    const float4 er = g_er4[node];

    float s0 = 0.f, s1 = 0.f, s2 = 0.f;
    float a0 = 0.f, a1 = 0.f, a2 = 0.f, a3 = 0.f, a4 = 0.f, a5 = 0.f;

    for (int b = begin; b < end; b += 32) {
        int i = b + lane;
        int mys = (i < end) ? g_csrsrc[i] : 0;
        int cnt = end - b; if (cnt > 32) cnt = 32;
        #pragma unroll 4
        for (int j = 0; j < cnt; j++) {
            int s = __shfl_sync(0xffffffffu, mys, j);
            float4 el = g_el4[s];                   // one LDG.128 broadcast
            float e0 = __expf(leaky(el.x + er.x));
            float e1 = __expf(leaky(el.y + er.y));
            float e2 = __expf(leaky(el.z + er.z));
            s0 += e0; s1 += e1; s2 += e2;
            const __nv_bfloat162* fr = &g_featb[(size_t)s * 96];
            float2 f0 = __bfloat1622float2(fr[lane]);       // head0 dims 2l,2l+1
            float2 f1 = __bfloat1622float2(fr[32 + lane]);  // head1
            float2 f2 = __bfloat1622float2(fr[64 + lane]);  // head2
            a0 += e0 * f0.x;  a1 += e0 * f0.y;
            a2 += e1 * f1.x;  a3 += e1 * f1.y;
            a4 += e2 * f2.x;  a5 += e2 * f2.y;
        }
    }

    const bool has = end > begin;
    const float i0 = has ? 1.f / s0 : 0.f;
    const float i1 = has ? 1.f / s1 : 0.f;
    const float i2 = has ? 1.f / s2 : 0.f;

    const int d0 = 2 * lane, d1 = 2 * lane + 1;
    const float third = 1.f / 3.f;
    float hd0 = (a0 * i0 + a2 * i1 + a4 * i2
                 + bias[d0] + bias[64 + d0] + bias[128 + d0]) * third;
    float hd1 = (a1 * i0 + a3 * i1 + a5 * i2
                 + bias[d1] + bias[64 + d1] + bias[128 + d1]) * third;

    const int g = graph_id[node];
    atomicAdd(&g_pool[g * HID + d0], hd0);
    atomicAdd(&g_pool[g * HID + d1], hd1);
    if (lane == 0) atomicAdd(&g_gcount[g], 1.f);
}

// ---------------- K4: final MLP + sigmoid ----------------
__global__ void k_final(
    const float* __restrict__ z, const float* __restrict__ lin1_w,
    const float* __restrict__ lin1_b, const float* __restrict__ lin2_w,
    const float* __restrict__ lin2_b, float* __restrict__ out, int G)
{
    const int w = threadIdx.x >> 5;
    const int lane = threadIdx.x & 31;
    if (w >= G) return;

    float z1a = lin1_b[lane], z1b = lin1_b[lane + 32];
    const float* zr = &z[w * 128];
    const float* w1a = &lin1_w[lane * 128];
    const float* w1b = &lin1_w[(lane + 32) * 128];
    #pragma unroll 4
    for (int k = 0; k < 128; k++) {
        float zv = zr[k];
        z1a += zv * w1a[k];
        z1b += zv * w1b[k];
    }

    float cnt = g_gcount[w];
    float invc = 1.f / fmaxf(cnt, 1.f);
    float pa = g_pool[w * HID + lane] * invc;
    float pb = g_pool[w * HID + 32 + lane] * invc;

    float part = lin2_w[lane] * pa + lin2_w[32 + lane] * pb
               + lin2_w[64 + lane] * z1a + lin2_w[96 + lane] * z1b;
    #pragma unroll
    for (int o = 16; o > 0; o >>= 1)
        part += __shfl_down_sync(0xffffffffu, part, o);

    if (lane == 0) {
        float v = part + lin2_b[0];
        out[w] = 1.f / (1.f + expf(-v));
    }
}

// ---------------- launch ----------------
extern "C" void kernel_launch(void* const* d_in, const int* in_sizes, int n_in,
                              void* d_out, int out_size)
{
    const float* h        = (const float*)d_in[0];
    const float* z        = (const float*)d_in[1];
    const int*   src      = (const int*)  d_in[2];
    const int*   dst      = (const int*)  d_in[3];
    const int*   graph_id = (const int*)  d_in[4];
    const float* fc_w     = (const float*)d_in[5];
    const float* attn_l   = (const float*)d_in[6];
    const float* attn_r   = (const float*)d_in[7];
    const float* bias     = (const float*)d_in[8];
    const float* lin1_w   = (const float*)d_in[9];
    const float* lin1_b   = (const float*)d_in[10];
    const float* lin2_w   = (const float*)d_in[11];
    const float* lin2_b   = (const float*)d_in[12];

    const int N = in_sizes[0] / NODE_DIM;   // 50000
    const int E = in_sizes[2];              // 800000
    const int G = in_sizes[1] / 128;        // 16
    const int NB = (N + SCAN_B - 1) / SCAN_B;  // 49

    cudaFuncSetAttribute(k_gemm, cudaFuncAttributeMaxDynamicSharedMemorySize,
                         K1_SMEM_BYTES);

    // Order chosen so the 4th launch (ncu's profiled slot) is k_gemm.
    // GEMM is independent of the CSR chain, so interleaving is legal.
    k_init<<<64, 256>>>(N, G);                                        // 1
    k_degree<<<(E + 255) / 256, 256>>>(dst, E);                       // 2
    k_scan_partial<<<NB, SCAN_B>>>(N);                                // 3
    k_gemm<<<(N + 127) / 128, 128, K1_SMEM_BYTES>>>(h, fc_w,          // 4
                                                    attn_l, attn_r, N);
    k_scan_final<<<NB, SCAN_B>>>(N);                                  // 5
    k_scatter<<<(E + 255) / 256, 256>>>(src, dst, E);                 // 6
    k_gat<<<(N * 32 + 255) / 256, 256>>>(graph_id, bias, N);          // 7
    k_final<<<1, 32 * G>>>(z, lin1_w, lin1_b, lin2_w, lin2_b,         // 8
                           (float*)d_out, G);
}

// round 7
// speedup vs baseline: 1.3177x; 1.1455x over previous
#include <cuda_runtime.h>
#include <cuda_bf16.h>
#include <math.h>

// Problem constants (shapes fixed by the reference)
#define MAX_N 50000
#define MAX_E 800000
#define MAX_G 16
#define NODE_DIM 128
#define HID 64
#define HEADS 3
#define FDIM 192            // HEADS*HID
#define NEG_SLOPE 0.2f
#define SCAN_B 1024
#define MAX_BLKS 64         // ceil(50000/1024)=49

// ---------------- device scratch (static, no runtime alloc) ----------------
__device__ __nv_bfloat162 g_featb[(size_t)MAX_N * 96];  // 19.2 MB (bf16 feat)
__device__ float4 g_el4[MAX_N];                          // padded el (x,y,z used)
__device__ float4 g_er4[MAX_N];
__device__ int    g_deg[MAX_N];
__device__ int    g_bsum[MAX_BLKS];
__device__ int    g_rowoff[MAX_N + 1];
__device__ int    g_cursor[MAX_N];
__device__ int    g_csrsrc[MAX_E];
__device__ float  g_pool[MAX_G * HID];
__device__ float  g_gcount[MAX_G];

// ---------------- helpers ----------------
__device__ __forceinline__ void fma2(unsigned long long& d,
                                     unsigned long long a,
                                     unsigned long long b) {
    asm("fma.rn.f32x2 %0, %1, %2, %0;" : "+l"(d) : "l"(a), "l"(b));
}
__device__ __forceinline__ unsigned long long pack2(float f) {
    unsigned long long r;
    asm("mov.b64 %0, {%1, %1};" : "=l"(r) : "f"(f));
    return r;
}
__device__ __forceinline__ float leaky(float x) {
    return x > 0.f ? x : NEG_SLOPE * x;
}

// ---------------- init (split so k_degree lands in profile slot 4) --------
__global__ void k_init_deg(int N) {
    int i = blockIdx.x * blockDim.x + threadIdx.x;
    int stride = gridDim.x * blockDim.x;
    for (int j = i; j < N; j += stride) g_deg[j] = 0;
}
__global__ void k_init_pool(int G) {
    int i = blockIdx.x * blockDim.x + threadIdx.x;
    if (i < G * HID) g_pool[i] = 0.f;
    if (i < G) g_gcount[i] = 0.f;
}

// ---------------- K1: register-tiled FFMA2 GEMM, fused el/er, bf16 out ----
// BM=64 nodes, BN=192 (all cols), BK=32, 256 threads.
// warp ng (0..7) owns nodes base+8ng..+7; lane cg owns cols 6cg..6cg+5.
// h_s[k][node] stride 68 (float4-aligned, conflict-free broadcast reads);
// w_s[k][col]  stride 194 (LDS.64-aligned reads).
#define GM_BM 64
#define GM_HS 68
#define GM_WS 194

__global__ void __launch_bounds__(256, 2) k_gemm(
    const float* __restrict__ h, const float* __restrict__ fc_w,
    const float* __restrict__ attn_l, const float* __restrict__ attn_r, int N)
{
    __shared__ float h_s[32 * GM_HS];
    __shared__ float w_s[32 * GM_WS];

    const int tid = threadIdx.x;
    const int ng = tid >> 5;          // warp id: node group
    const int cg = tid & 31;          // lane: col group (6 cols)
    const int base = blockIdx.x * GM_BM;

    const float4* h4 = (const float4*)h;      // [N][32]
    const float4* w4 = (const float4*)fc_w;   // [192][32]

    // acc2[mp][j]: packed fp32x2 over node pair (2mp, 2mp+1), col 6cg+j
    unsigned long long acc2[4][6];
    #pragma unroll
    for (int mp = 0; mp < 4; mp++)
        #pragma unroll
        for (int j = 0; j < 6; j++) acc2[mp][j] = 0ull;

    #pragma unroll
    for (int chunk = 0; chunk < 4; chunk++) {
        if (chunk) __syncthreads();
        // stage h: 64 nodes x 32 k = 512 float4, 2 per thread (coalesced)
        #pragma unroll
        for (int i = 0; i < 2; i++) {
            int F = i * 256 + tid;
            int nd = F >> 3, kq = F & 7;
            int gn = base + nd;
            float4 v = (gn < N) ? h4[(size_t)gn * 32 + chunk * 8 + kq]
                                : make_float4(0.f, 0.f, 0.f, 0.f);
            h_s[(kq * 4 + 0) * GM_HS + nd] = v.x;
            h_s[(kq * 4 + 1) * GM_HS + nd] = v.y;
            h_s[(kq * 4 + 2) * GM_HS + nd] = v.z;
            h_s[(kq * 4 + 3) * GM_HS + nd] = v.w;
        }
        // stage w: 192 cols x 32 k = 1536 float4, 6 per thread (coalesced)
        #pragma unroll
        for (int i = 0; i < 6; i++) {
            int F = i * 256 + tid;
            int c = F >> 3, kq = F & 7;
            float4 v = w4[c * 32 + chunk * 8 + kq];
            w_s[(kq * 4 + 0) * GM_WS + c] = v.x;
            w_s[(kq * 4 + 1) * GM_WS + c] = v.y;
            w_s[(kq * 4 + 2) * GM_WS + c] = v.z;
            w_s[(kq * 4 + 3) * GM_WS + c] = v.w;
        }
        __syncthreads();

        #pragma unroll 2
        for (int k = 0; k < 32; k++) {
            float4 ha = *(const float4*)&h_s[k * GM_HS + ng * 8];
            float4 hb = *(const float4*)&h_s[k * GM_HS + ng * 8 + 4];
            unsigned long long hp[4];
            hp[0] = *(unsigned long long*)&ha.x;
            hp[1] = *(unsigned long long*)&ha.z;
            hp[2] = *(unsigned long long*)&hb.x;
            hp[3] = *(unsigned long long*)&hb.z;
            const float* wr = &w_s[k * GM_WS + 6 * cg];
            #pragma unroll
            for (int j = 0; j < 6; j++) {
                unsigned long long wp = pack2(wr[j]);
                fma2(acc2[0][j], hp[0], wp);
                fma2(acc2[1][j], hp[1], wp);
                fma2(acc2[2][j], hp[2], wp);
                fma2(acc2[3][j], hp[3], wp);
            }
        }
    }

    // ---- epilogue: bf16 feat stores + warp-reduced el/er ----
    float alr[6], arr[6];
    #pragma unroll
    for (int j = 0; j < 6; j++) {
        alr[j] = __ldg(&attn_l[6 * cg + j]);
        arr[j] = __ldg(&attn_r[6 * cg + j]);
    }

    #pragma unroll
    for (int mp = 0; mp < 4; mp++) {
        #pragma unroll
        for (int half = 0; half < 2; half++) {
            const int node = base + ng * 8 + 2 * mp + half;
            float v[6];
            #pragma unroll
            for (int j = 0; j < 6; j++) {
                float2 f = *(float2*)&acc2[mp][j];
                v[j] = half ? f.y : f.x;
            }
            // per-head el/er partials (cols 6cg..6cg+5 touch <=2 heads)
            float e0 = 0.f, e1 = 0.f, e2 = 0.f;
            float r0 = 0.f, r1 = 0.f, r2 = 0.f;
            #pragma unroll
            for (int j = 0; j < 6; j++) {
                int hd = (6 * cg + j) >> 6;
                float tl = v[j] * alr[j], tr = v[j] * arr[j];
                if (hd == 0)      { e0 += tl; r0 += tr; }
                else if (hd == 1) { e1 += tl; r1 += tr; }
                else              { e2 += tl; r2 += tr; }
            }
            #pragma unroll
            for (int o = 16; o > 0; o >>= 1) {
                e0 += __shfl_down_sync(0xffffffffu, e0, o);
                e1 += __shfl_down_sync(0xffffffffu, e1, o);
                e2 += __shfl_down_sync(0xffffffffu, e2, o);
                r0 += __shfl_down_sync(0xffffffffu, r0, o);
                r1 += __shfl_down_sync(0xffffffffu, r1, o);
                r2 += __shfl_down_sync(0xffffffffu, r2, o);
            }
            if (node < N) {
                if (cg == 0) {
                    g_el4[node] = make_float4(e0, e1, e2, 0.f);
                    g_er4[node] = make_float4(r0, r1, r2, 0.f);
                }
                __nv_bfloat162* fo = &g_featb[(size_t)node * 96 + 3 * cg];
                fo[0] = __floats2bfloat162_rn(v[0], v[1]);
                fo[1] = __floats2bfloat162_rn(v[2], v[3]);
                fo[2] = __floats2bfloat162_rn(v[4], v[5]);
            }
        }
    }
}

// ---------------- CSR phase 1: degree histogram ----------------
__global__ void k_degree(const int* __restrict__ dst, int E) {
    int i = blockIdx.x * blockDim.x + threadIdx.x;
    if (i < E) atomicAdd(&g_deg[dst[i]], 1);
}

// ---------------- CSR phase 2a: per-block (1024-tile) sums ----------------
__global__ void __launch_bounds__(SCAN_B) k_scan_partial(int N) {
    __shared__ int ws[32];
    const int t = threadIdx.x, lane = t & 31, w = t >> 5;
    int idx = blockIdx.x * SCAN_B + t;
    int v = (idx < N) ? g_deg[idx] : 0;
    #pragma unroll
    for (int o = 16; o > 0; o >>= 1) v += __shfl_down_sync(0xffffffffu, v, o);
    if (lane == 0) ws[w] = v;
    __syncthreads();
    if (w == 0) {
        int s = ws[lane];
        #pragma unroll
        for (int o = 16; o > 0; o >>= 1) s += __shfl_down_sync(0xffffffffu, s, o);
        if (lane == 0) g_bsum[blockIdx.x] = s;
    }
}

// ---------------- CSR phase 2b: block-local scan + top-scan + write --------
__global__ void __launch_bounds__(SCAN_B) k_scan_final(int N) {
    __shared__ int soff[MAX_BLKS];
    __shared__ int wsum[32];
    const int t = threadIdx.x, lane = t & 31, w = t >> 5;
    const int nb = gridDim.x;

    if (w == 0) {
        int v0 = (lane < nb) ? g_bsum[lane] : 0;
        int v1 = (lane + 32 < nb) ? g_bsum[lane + 32] : 0;
        int s0 = v0, s1 = v1;
        #pragma unroll
        for (int o = 1; o < 32; o <<= 1) {
            int y = __shfl_up_sync(0xffffffffu, s0, o);
            if (lane >= o) s0 += y;
            int y1 = __shfl_up_sync(0xffffffffu, s1, o);
            if (lane >= o) s1 += y1;
        }
        int tot0 = __shfl_sync(0xffffffffu, s0, 31);
        s1 += tot0;
        soff[lane] = s0 - v0;
        soff[lane + 32] = s1 - v1;
    }
    __syncthreads();
    const int off = soff[blockIdx.x];

    int idx = blockIdx.x * SCAN_B + t;
    int v = (idx < N) ? g_deg[idx] : 0;
    int x = v;
    #pragma unroll
    for (int o = 1; o < 32; o <<= 1) {
        int y = __shfl_up_sync(0xffffffffu, x, o);
        if (lane >= o) x += y;
    }
    if (lane == 31) wsum[w] = x;
    __syncthreads();
    if (w == 0) {
        int s = wsum[lane], sc = s;
        #pragma unroll
        for (int o = 1; o < 32; o <<= 1) {
            int y = __shfl_up_sync(0xffffffffu, sc, o);
            if (lane >= o) sc += y;
        }
        wsum[lane] = sc - s;
    }
    __syncthreads();

    int excl = (x - v) + wsum[w] + off;
    if (idx < N) {
        g_rowoff[idx] = excl;
        g_cursor[idx] = excl;
        if (idx == N - 1) g_rowoff[N] = excl + v;
    }
}

// ---------------- CSR phase 3: scatter ----------------
__global__ void k_scatter(const int* __restrict__ src, const int* __restrict__ dst, int E) {
    int i = blockIdx.x * blockDim.x + threadIdx.x;
    if (i < E) {
        int d = dst[i];
        int pos = atomicAdd(&g_cursor[d], 1);
        g_csrsrc[pos] = src[i];
    }
}

// ---------------- K3: fused GAT softmax + aggregation + pool (1 pass) ------
__global__ void __launch_bounds__(256) k_gat(
    const int* __restrict__ graph_id, const float* __restrict__ bias, int N)
{
    const int node = (blockIdx.x * blockDim.x + threadIdx.x) >> 5;
    const int lane = threadIdx.x & 31;
    if (node >= N) return;
    const int begin = g_rowoff[node];
    const int end   = g_rowoff[node + 1];

    const float4 er = g_er4[node];

    float s0 = 0.f, s1 = 0.f, s2 = 0.f;
    float a0 = 0.f, a1 = 0.f, a2 = 0.f, a3 = 0.f, a4 = 0.f, a5 = 0.f;

    for (int b = begin; b < end; b += 32) {
        int i = b + lane;
        int mys = (i < end) ? g_csrsrc[i] : 0;
        int cnt = end - b; if (cnt > 32) cnt = 32;
        #pragma unroll 4
        for (int j = 0; j < cnt; j++) {
            int s = __shfl_sync(0xffffffffu, mys, j);
            float4 el = g_el4[s];
            float e0 = __expf(leaky(el.x + er.x));
            float e1 = __expf(leaky(el.y + er.y));
            float e2 = __expf(leaky(el.z + er.z));
            s0 += e0; s1 += e1; s2 += e2;
            const __nv_bfloat162* fr = &g_featb[(size_t)s * 96];
            float2 f0 = __bfloat1622float2(fr[lane]);
            float2 f1 = __bfloat1622float2(fr[32 + lane]);
            float2 f2 = __bfloat1622float2(fr[64 + lane]);
            a0 += e0 * f0.x;  a1 += e0 * f0.y;
            a2 += e1 * f1.x;  a3 += e1 * f1.y;
            a4 += e2 * f2.x;  a5 += e2 * f2.y;
        }
    }

    const bool has = end > begin;
    const float i0 = has ? 1.f / s0 : 0.f;
    const float i1 = has ? 1.f / s1 : 0.f;
    const float i2 = has ? 1.f / s2 : 0.f;

    const int d0 = 2 * lane, d1 = 2 * lane + 1;
    const float third = 1.f / 3.f;
    float hd0 = (a0 * i0 + a2 * i1 + a4 * i2
                 + bias[d0] + bias[64 + d0] + bias[128 + d0]) * third;
    float hd1 = (a1 * i0 + a3 * i1 + a5 * i2
                 + bias[d1] + bias[64 + d1] + bias[128 + d1]) * third;

    const int g = graph_id[node];
    atomicAdd(&g_pool[g * HID + d0], hd0);
    atomicAdd(&g_pool[g * HID + d1], hd1);
    if (lane == 0) atomicAdd(&g_gcount[g], 1.f);
}

// ---------------- K4: final MLP + sigmoid ----------------
__global__ void k_final(
    const float* __restrict__ z, const float* __restrict__ lin1_w,
    const float* __restrict__ lin1_b, const float* __restrict__ lin2_w,
    const float* __restrict__ lin2_b, float* __restrict__ out, int G)
{
    const int w = threadIdx.x >> 5;
    const int lane = threadIdx.x & 31;
    if (w >= G) return;

    float z1a = lin1_b[lane], z1b = lin1_b[lane + 32];
    const float* zr = &z[w * 128];
    const float* w1a = &lin1_w[lane * 128];
    const float* w1b = &lin1_w[(lane + 32) * 128];
    #pragma unroll 4
    for (int k = 0; k < 128; k++) {
        float zv = zr[k];
        z1a += zv * w1a[k];
        z1b += zv * w1b[k];
    }

    float cnt = g_gcount[w];
    float invc = 1.f / fmaxf(cnt, 1.f);
    float pa = g_pool[w * HID + lane] * invc;
    float pb = g_pool[w * HID + 32 + lane] * invc;

    float part = lin2_w[lane] * pa + lin2_w[32 + lane] * pb
               + lin2_w[64 + lane] * z1a + lin2_w[96 + lane] * z1b;
    #pragma unroll
    for (int o = 16; o > 0; o >>= 1)
        part += __shfl_down_sync(0xffffffffu, part, o);

    if (lane == 0) {
        float v = part + lin2_b[0];
        out[w] = 1.f / (1.f + expf(-v));
    }
}

// ---------------- launch ----------------
extern "C" void kernel_launch(void* const* d_in, const int* in_sizes, int n_in,
                              void* d_out, int out_size)
{
    const float* h        = (const float*)d_in[0];
    const float* z        = (const float*)d_in[1];
    const int*   src      = (const int*)  d_in[2];
    const int*   dst      = (const int*)  d_in[3];
    const int*   graph_id = (const int*)  d_in[4];
    const float* fc_w     = (const float*)d_in[5];
    const float* attn_l   = (const float*)d_in[6];
    const float* attn_r   = (const float*)d_in[7];
    const float* bias     = (const float*)d_in[8];
    const float* lin1_w   = (const float*)d_in[9];
    const float* lin1_b   = (const float*)d_in[10];
    const float* lin2_w   = (const float*)d_in[11];
    const float* lin2_b   = (const float*)d_in[12];

    const int N = in_sizes[0] / NODE_DIM;   // 50000
    const int E = in_sizes[2];              // 800000
    const int G = in_sizes[1] / 128;        // 16
    const int NB = (N + SCAN_B - 1) / SCAN_B;  // 49

    // Launch order: slot 4 (the ncu-profiled launch) = k_degree.
    k_init_deg<<<64, 256>>>(N);                                       // 1
    k_init_pool<<<4, 256>>>(G);                                       // 2
    k_gemm<<<(N + GM_BM - 1) / GM_BM, 256>>>(h, fc_w,                 // 3
                                             attn_l, attn_r, N);
    k_degree<<<(E + 255) / 256, 256>>>(dst, E);                       // 4
    k_scan_partial<<<NB, SCAN_B>>>(N);                                // 5
    k_scan_final<<<NB, SCAN_B>>>(N);                                  // 6
    k_scatter<<<(E + 255) / 256, 256>>>(src, dst, E);                 // 7
    k_gat<<<(N * 32 + 255) / 256, 256>>>(graph_id, bias, N);          // 8
    k_final<<<1, 32 * G>>>(z, lin1_w, lin1_b, lin2_w, lin2_b,         // 9
                           (float*)d_out, G);
}

// round 8
// speedup vs baseline: 1.3440x; 1.0199x over previous
#include <cuda_runtime.h>
#include <cuda_bf16.h>
#include <math.h>

// Problem constants (shapes fixed by the reference)
#define MAX_N 50000
#define MAX_E 800000
#define MAX_G 16
#define NODE_DIM 128
#define HID 64
#define HEADS 3
#define FDIM 192            // HEADS*HID
#define NEG_SLOPE 0.2f
#define SCAN_B 1024
#define MAX_BLKS 64         // ceil(50000/1024)=49

// ------------- device scratch (static; zero-init from BSS at load) --------
// Invariant: g_deg, g_pool, g_gcount are ZERO on entry to kernel_launch and
// are re-zeroed by their consumers each run (self-cleaning), so no init
// kernels are needed and every graph replay sees identical state.
__device__ __nv_bfloat162 g_featb[(size_t)MAX_N * 96];  // 19.2 MB (bf16 feat)
__device__ float4 g_el4[MAX_N];                          // padded el (x,y,z used)
__device__ float4 g_er4[MAX_N];
__device__ int    g_deg[MAX_N];
__device__ int    g_bsum[MAX_BLKS];
__device__ int    g_rowoff[MAX_N + 1];
__device__ int    g_cursor[MAX_N];
__device__ int    g_csrsrc[MAX_E];
__device__ float  g_pool[MAX_G * HID];
__device__ float  g_gcount[MAX_G];

// ---------------- helpers ----------------
__device__ __forceinline__ void fma2(unsigned long long& d,
                                     unsigned long long a,
                                     unsigned long long b) {
    asm("fma.rn.f32x2 %0, %1, %2, %0;" : "+l"(d) : "l"(a), "l"(b));
}
__device__ __forceinline__ unsigned long long pack2(float f) {
    unsigned long long r;
    asm("mov.b64 %0, {%1, %1};" : "=l"(r) : "f"(f));
    return r;
}
__device__ __forceinline__ float leaky(float x) {
    return x > 0.f ? x : NEG_SLOPE * x;
}

// ---------------- CSR phase 1: degree histogram ----------------
__global__ void k_degree(const int* __restrict__ dst, int E) {
    int i = blockIdx.x * blockDim.x + threadIdx.x;
    if (i < E) atomicAdd(&g_deg[dst[i]], 1);
}

// ---------------- CSR phase 2a: per-block (1024-tile) sums ----------------
__global__ void __launch_bounds__(SCAN_B) k_scan_partial(int N) {
    __shared__ int ws[32];
    const int t = threadIdx.x, lane = t & 31, w = t >> 5;
    int idx = blockIdx.x * SCAN_B + t;
    int v = (idx < N) ? g_deg[idx] : 0;
    #pragma unroll
    for (int o = 16; o > 0; o >>= 1) v += __shfl_down_sync(0xffffffffu, v, o);
    if (lane == 0) ws[w] = v;
    __syncthreads();
    if (w == 0) {
        int s = ws[lane];
        #pragma unroll
        for (int o = 16; o > 0; o >>= 1) s += __shfl_down_sync(0xffffffffu, s, o);
        if (lane == 0) g_bsum[blockIdx.x] = s;
    }
}

// ------ CSR phase 2b: block-local scan + top-scan + write (+deg reset) ----
__global__ void __launch_bounds__(SCAN_B) k_scan_final(int N) {
    __shared__ int soff[MAX_BLKS];
    __shared__ int wsum[32];
    const int t = threadIdx.x, lane = t & 31, w = t >> 5;
    const int nb = gridDim.x;

    if (w == 0) {
        int v0 = (lane < nb) ? g_bsum[lane] : 0;
        int v1 = (lane + 32 < nb) ? g_bsum[lane + 32] : 0;
        int s0 = v0, s1 = v1;
        #pragma unroll
        for (int o = 1; o < 32; o <<= 1) {
            int y = __shfl_up_sync(0xffffffffu, s0, o);
            if (lane >= o) s0 += y;
            int y1 = __shfl_up_sync(0xffffffffu, s1, o);
            if (lane >= o) s1 += y1;
        }
        int tot0 = __shfl_sync(0xffffffffu, s0, 31);
        s1 += tot0;
        soff[lane] = s0 - v0;
        soff[lane + 32] = s1 - v1;
    }
    __syncthreads();
    const int off = soff[blockIdx.x];

    int idx = blockIdx.x * SCAN_B + t;
    int v = (idx < N) ? g_deg[idx] : 0;
    int x = v;
    #pragma unroll
    for (int o = 1; o < 32; o <<= 1) {
        int y = __shfl_up_sync(0xffffffffu, x, o);
        if (lane >= o) x += y;
    }
    if (lane == 31) wsum[w] = x;
    __syncthreads();
    if (w == 0) {
        int s = wsum[lane], sc = s;
        #pragma unroll
        for (int o = 1; o < 32; o <<= 1) {
            int y = __shfl_up_sync(0xffffffffu, sc, o);
            if (lane >= o) sc += y;
        }
        wsum[lane] = sc - s;
    }
    __syncthreads();

    int excl = (x - v) + wsum[w] + off;
    if (idx < N) {
        g_rowoff[idx] = excl;
        g_cursor[idx] = excl;
        g_deg[idx] = 0;                       // self-clean for next run
        if (idx == N - 1) g_rowoff[N] = excl + v;
    }
}

// ---------------- CSR phase 3: scatter (profiled slot 4) ----------------
__global__ void k_scatter(const int* __restrict__ src, const int* __restrict__ dst, int E) {
    int i = blockIdx.x * blockDim.x + threadIdx.x;
    if (i < E) {
        int d = dst[i];
        int pos = atomicAdd(&g_cursor[d], 1);
        g_csrsrc[pos] = src[i];
    }
}

// ---------------- K1: register-tiled FFMA2 GEMM, fused el/er, bf16 out ----
#define GM_BM 64
#define GM_HS 68
#define GM_WS 194

__global__ void __launch_bounds__(256, 2) k_gemm(
    const float* __restrict__ h, const float* __restrict__ fc_w,
    const float* __restrict__ attn_l, const float* __restrict__ attn_r, int N)
{
    __shared__ float h_s[32 * GM_HS];
    __shared__ float w_s[32 * GM_WS];

    const int tid = threadIdx.x;
    const int ng = tid >> 5;
    const int cg = tid & 31;
    const int base = blockIdx.x * GM_BM;

    const float4* h4 = (const float4*)h;
    const float4* w4 = (const float4*)fc_w;

    unsigned long long acc2[4][6];
    #pragma unroll
    for (int mp = 0; mp < 4; mp++)
        #pragma unroll
        for (int j = 0; j < 6; j++) acc2[mp][j] = 0ull;

    #pragma unroll
    for (int chunk = 0; chunk < 4; chunk++) {
        if (chunk) __syncthreads();
        #pragma unroll
        for (int i = 0; i < 2; i++) {
            int F = i * 256 + tid;
            int nd = F >> 3, kq = F & 7;
            int gn = base + nd;
            float4 v = (gn < N) ? h4[(size_t)gn * 32 + chunk * 8 + kq]
                                : make_float4(0.f, 0.f, 0.f, 0.f);
            h_s[(kq * 4 + 0) * GM_HS + nd] = v.x;
            h_s[(kq * 4 + 1) * GM_HS + nd] = v.y;
            h_s[(kq * 4 + 2) * GM_HS + nd] = v.z;
            h_s[(kq * 4 + 3) * GM_HS + nd] = v.w;
        }
        #pragma unroll
        for (int i = 0; i < 6; i++) {
            int F = i * 256 + tid;
            int c = F >> 3, kq = F & 7;
            float4 v = w4[c * 32 + chunk * 8 + kq];
            w_s[(kq * 4 + 0) * GM_WS + c] = v.x;
            w_s[(kq * 4 + 1) * GM_WS + c] = v.y;
            w_s[(kq * 4 + 2) * GM_WS + c] = v.z;
            w_s[(kq * 4 + 3) * GM_WS + c] = v.w;
        }
        __syncthreads();

        #pragma unroll 2
        for (int k = 0; k < 32; k++) {
            float4 ha = *(const float4*)&h_s[k * GM_HS + ng * 8];
            float4 hb = *(const float4*)&h_s[k * GM_HS + ng * 8 + 4];
            unsigned long long hp[4];
            hp[0] = *(unsigned long long*)&ha.x;
            hp[1] = *(unsigned long long*)&ha.z;
            hp[2] = *(unsigned long long*)&hb.x;
            hp[3] = *(unsigned long long*)&hb.z;
            const float* wr = &w_s[k * GM_WS + 6 * cg];
            #pragma unroll
            for (int j = 0; j < 6; j++) {
                unsigned long long wp = pack2(wr[j]);
                fma2(acc2[0][j], hp[0], wp);
                fma2(acc2[1][j], hp[1], wp);
                fma2(acc2[2][j], hp[2], wp);
                fma2(acc2[3][j], hp[3], wp);
            }
        }
    }

    float alr[6], arr[6];
    #pragma unroll
    for (int j = 0; j < 6; j++) {
        alr[j] = __ldg(&attn_l[6 * cg + j]);
        arr[j] = __ldg(&attn_r[6 * cg + j]);
    }

    #pragma unroll
    for (int mp = 0; mp < 4; mp++) {
        #pragma unroll
        for (int half = 0; half < 2; half++) {
            const int node = base + ng * 8 + 2 * mp + half;
            float v[6];
            #pragma unroll
            for (int j = 0; j < 6; j++) {
                float2 f = *(float2*)&acc2[mp][j];
                v[j] = half ? f.y : f.x;
            }
            float e0 = 0.f, e1 = 0.f, e2 = 0.f;
            float r0 = 0.f, r1 = 0.f, r2 = 0.f;
            #pragma unroll
            for (int j = 0; j < 6; j++) {
                int hd = (6 * cg + j) >> 6;
                float tl = v[j] * alr[j], tr = v[j] * arr[j];
                if (hd == 0)      { e0 += tl; r0 += tr; }
                else if (hd == 1) { e1 += tl; r1 += tr; }
                else              { e2 += tl; r2 += tr; }
            }
            #pragma unroll
            for (int o = 16; o > 0; o >>= 1) {
                e0 += __shfl_down_sync(0xffffffffu, e0, o);
                e1 += __shfl_down_sync(0xffffffffu, e1, o);
                e2 += __shfl_down_sync(0xffffffffu, e2, o);
                r0 += __shfl_down_sync(0xffffffffu, r0, o);
                r1 += __shfl_down_sync(0xffffffffu, r1, o);
                r2 += __shfl_down_sync(0xffffffffu, r2, o);
            }
            if (node < N) {
                if (cg == 0) {
                    g_el4[node] = make_float4(e0, e1, e2, 0.f);
                    g_er4[node] = make_float4(r0, r1, r2, 0.f);
                }
                __nv_bfloat162* fo = &g_featb[(size_t)node * 96 + 3 * cg];
                fo[0] = __floats2bfloat162_rn(v[0], v[1]);
                fo[1] = __floats2bfloat162_rn(v[2], v[3]);
                fo[2] = __floats2bfloat162_rn(v[4], v[5]);
            }
        }
    }
}

// ---------------- K3: fused GAT softmax + aggregation + pool --------------
// warp per destination node; lane-parallel exp (3 MUFU per 32 edges instead
// of per edge), shfl-broadcast (src, e0..e2); softmax sums accumulated
// lane-locally and warp-reduced once.
__global__ void __launch_bounds__(256) k_gat(
    const int* __restrict__ graph_id, const float* __restrict__ bias, int N)
{
    const int node = (blockIdx.x * blockDim.x + threadIdx.x) >> 5;
    const int lane = threadIdx.x & 31;
    if (node >= N) return;
    const int begin = g_rowoff[node];
    const int end   = g_rowoff[node + 1];

    const float4 er = g_er4[node];

    float s0 = 0.f, s1 = 0.f, s2 = 0.f;   // lane-local exp sums
    float a0 = 0.f, a1 = 0.f, a2 = 0.f, a3 = 0.f, a4 = 0.f, a5 = 0.f;

    for (int b = begin; b < end; b += 32) {
        const int i = b + lane;
        const bool act = i < end;
        int mys = act ? g_csrsrc[i] : 0;
        float4 el = g_el4[mys];
        float ex0 = __expf(leaky(el.x + er.x));
        float ex1 = __expf(leaky(el.y + er.y));
        float ex2 = __expf(leaky(el.z + er.z));
        if (act) { s0 += ex0; s1 += ex1; s2 += ex2; }

        int cnt = end - b; if (cnt > 32) cnt = 32;
        #pragma unroll 4
        for (int j = 0; j < cnt; j++) {
            int   s  = __shfl_sync(0xffffffffu, mys, j);
            float e0 = __shfl_sync(0xffffffffu, ex0, j);
            float e1 = __shfl_sync(0xffffffffu, ex1, j);
            float e2 = __shfl_sync(0xffffffffu, ex2, j);
            const __nv_bfloat162* fr = &g_featb[(size_t)s * 96];
            float2 f0 = __bfloat1622float2(__ldg(&fr[lane]));
            float2 f1 = __bfloat1622float2(__ldg(&fr[32 + lane]));
            float2 f2 = __bfloat1622float2(__ldg(&fr[64 + lane]));
            a0 += e0 * f0.x;  a1 += e0 * f0.y;
            a2 += e1 * f1.x;  a3 += e1 * f1.y;
            a4 += e2 * f2.x;  a5 += e2 * f2.y;
        }
    }

    // reduce exp sums across lanes (all lanes need them)
    #pragma unroll
    for (int o = 16; o > 0; o >>= 1) {
        s0 += __shfl_xor_sync(0xffffffffu, s0, o);
        s1 += __shfl_xor_sync(0xffffffffu, s1, o);
        s2 += __shfl_xor_sync(0xffffffffu, s2, o);
    }

    const bool has = end > begin;
    const float i0 = has ? 1.f / s0 : 0.f;
    const float i1 = has ? 1.f / s1 : 0.f;
    const float i2 = has ? 1.f / s2 : 0.f;

    const int d0 = 2 * lane, d1 = 2 * lane + 1;
    const float third = 1.f / 3.f;
    float hd0 = (a0 * i0 + a2 * i1 + a4 * i2
                 + bias[d0] + bias[64 + d0] + bias[128 + d0]) * third;
    float hd1 = (a1 * i0 + a3 * i1 + a5 * i2
                 + bias[d1] + bias[64 + d1] + bias[128 + d1]) * third;

    const int g = graph_id[node];
    atomicAdd(&g_pool[g * HID + d0], hd0);
    atomicAdd(&g_pool[g * HID + d1], hd1);
    if (lane == 0) atomicAdd(&g_gcount[g], 1.f);
}

// ---------------- K4: final MLP + sigmoid (+ pool reset) ----------------
__global__ void k_final(
    const float* __restrict__ z, const float* __restrict__ lin1_w,
    const float* __restrict__ lin1_b, const float* __restrict__ lin2_w,
    const float* __restrict__ lin2_b, float* __restrict__ out, int G)
{
    const int w = threadIdx.x >> 5;
    const int lane = threadIdx.x & 31;
    if (w >= G) return;

    float z1a = lin1_b[lane], z1b = lin1_b[lane + 32];
    const float* zr = &z[w * 128];
    const float* w1a = &lin1_w[lane * 128];
    const float* w1b = &lin1_w[(lane + 32) * 128];
    #pragma unroll 4
    for (int k = 0; k < 128; k++) {
        float zv = zr[k];
        z1a += zv * w1a[k];
        z1b += zv * w1b[k];
    }

    float cnt = g_gcount[w];
    float invc = 1.f / fmaxf(cnt, 1.f);
    float pa = g_pool[w * HID + lane] * invc;
    float pb = g_pool[w * HID + 32 + lane] * invc;

    // self-clean for next run (reads above complete before these writes)
    g_pool[w * HID + lane] = 0.f;
    g_pool[w * HID + 32 + lane] = 0.f;
    if (lane == 0) g_gcount[w] = 0.f;

    float part = lin2_w[lane] * pa + lin2_w[32 + lane] * pb
               + lin2_w[64 + lane] * z1a + lin2_w[96 + lane] * z1b;
    #pragma unroll
    for (int o = 16; o > 0; o >>= 1)
        part += __shfl_down_sync(0xffffffffu, part, o);

    if (lane == 0) {
        float v = part + lin2_b[0];
        out[w] = 1.f / (1.f + expf(-v));
    }
}

// ---------------- launch ----------------
extern "C" void kernel_launch(void* const* d_in, const int* in_sizes, int n_in,
                              void* d_out, int out_size)
{
    const float* h        = (const float*)d_in[0];
    const float* z        = (const float*)d_in[1];
    const int*   src      = (const int*)  d_in[2];
    const int*   dst      = (const int*)  d_in[3];
    const int*   graph_id = (const int*)  d_in[4];
    const float* fc_w     = (const float*)d_in[5];
    const float* attn_l   = (const float*)d_in[6];
    const float* attn_r   = (const float*)d_in[7];
    const float* bias     = (const float*)d_in[8];
    const float* lin1_w   = (const float*)d_in[9];
    const float* lin1_b   = (const float*)d_in[10];
    const float* lin2_w   = (const float*)d_in[11];
    const float* lin2_b   = (const float*)d_in[12];

    const int N = in_sizes[0] / NODE_DIM;   // 50000
    const int E = in_sizes[2];              // 800000
    const int G = in_sizes[1] / 128;        // 16
    const int NB = (N + SCAN_B - 1) / SCAN_B;  // 49

    // Launch order: slot 4 (the ncu-profiled launch) = k_scatter.
    k_degree<<<(E + 255) / 256, 256>>>(dst, E);                       // 1
    k_scan_partial<<<NB, SCAN_B>>>(N);                                // 2
    k_scan_final<<<NB, SCAN_B>>>(N);                                  // 3
    k_scatter<<<(E + 255) / 256, 256>>>(src, dst, E);                 // 4
    k_gemm<<<(N + GM_BM - 1) / GM_BM, 256>>>(h, fc_w,                 // 5
                                             attn_l, attn_r, N);
    k_gat<<<(N * 32 + 255) / 256, 256>>>(graph_id, bias, N);          // 6
    k_final<<<1, 32 * G>>>(z, lin1_w, lin1_b, lin2_w, lin2_b,         // 7
                           (float*)d_out, G);
}